// round 3
// baseline (speedup 1.0000x reference)
#include <cuda_runtime.h>
#include <cstdint>
#include <cstddef>

// Problem constants
#define BATCH  32
#define SEQ    1024
#define INDIM  128
#define HID    512
#define LAYERS 3

// Persistent-recurrence decomposition
#define GB 16   // batch groups (2 batches each)
#define GJ 8    // j (output-column) groups (64 columns each)

// ---------------- device scratch (allocation-free rule: __device__ globals) ----
__device__ float g_P[(size_t)BATCH * SEQ * HID];   // pre-activations for current layer (64 MB)
__device__ float g_O[(size_t)BATCH * SEQ * HID];   // layer output sequence (64 MB, reused)
__device__ float g_hbuf[2][BATCH * HID];           // double-buffered hidden state
__device__ int   g_flags[GB * GJ];                 // per-CTA step flags

// ---------------- memory-order helpers ----------------------------------------
__device__ __forceinline__ int ld_acquire_gpu(const int* p) {
    int v;
    asm volatile("ld.global.acquire.gpu.b32 %0, [%1];" : "=r"(v) : "l"(p));
    return v;
}
__device__ __forceinline__ void st_relaxed_gpu(int* p, int v) {
    asm volatile("st.global.relaxed.gpu.b32 [%0], %1;" :: "l"(p), "r"(v));
}

// ==============================================================================
// Projection GEMM:  g_P[r][n] = sum_k A[r][k] * W[n][k] + bias[n]
// A: [M=32768, K] row-major (x or g_O), W: [512, K] row-major, K in {128, 512}
// 128x128 block tile, BK=8, 256 threads, 8x8 microtile.
// Block (0,0) also resets the recurrence flags (stream order guarantees this
// lands before the next recurrence kernel).
// ==============================================================================
__global__ __launch_bounds__(256) void proj_kernel(
    const float* __restrict__ Aext, int useO,
    const float* __restrict__ W,
    const float* __restrict__ bias,
    int K)
{
    const float* A = useO ? g_O : Aext;

    __shared__ float As[8][128];
    __shared__ float Bs[8][128];

    int tid = threadIdx.x;
    if (blockIdx.x == 0 && blockIdx.y == 0 && tid < GB * GJ) g_flags[tid] = 0;

    int m0 = blockIdx.y * 128;
    int n0 = blockIdx.x * 128;

    int lr = tid >> 1;            // 0..127: row within tile
    int lk = (tid & 1) * 4;       // 0 or 4: k sub-offset

    const float4* Aload = (const float4*)(A + (size_t)(m0 + lr) * K + lk);
    const float4* Wload = (const float4*)(W + (size_t)(n0 + lr) * K + lk);

    int tm = tid >> 4;            // 0..15
    int tn = tid & 15;            // 0..15

    float acc[8][8];
    #pragma unroll
    for (int i = 0; i < 8; i++)
        #pragma unroll
        for (int j = 0; j < 8; j++) acc[i][j] = 0.f;

    for (int k0 = 0; k0 < K; k0 += 8) {
        float4 av = Aload[k0 >> 2];
        float4 wv = Wload[k0 >> 2];
        As[lk + 0][lr] = av.x; As[lk + 1][lr] = av.y;
        As[lk + 2][lr] = av.z; As[lk + 3][lr] = av.w;
        Bs[lk + 0][lr] = wv.x; Bs[lk + 1][lr] = wv.y;
        Bs[lk + 2][lr] = wv.z; Bs[lk + 3][lr] = wv.w;
        __syncthreads();

        #pragma unroll
        for (int kk = 0; kk < 8; kk++) {
            float a[8], b[8];
            *(float4*)(a)     = *(const float4*)(&As[kk][tm * 8]);
            *(float4*)(a + 4) = *(const float4*)(&As[kk][tm * 8 + 4]);
            *(float4*)(b)     = *(const float4*)(&Bs[kk][tn * 8]);
            *(float4*)(b + 4) = *(const float4*)(&Bs[kk][tn * 8 + 4]);
            #pragma unroll
            for (int i = 0; i < 8; i++)
                #pragma unroll
                for (int j = 0; j < 8; j++)
                    acc[i][j] += a[i] * b[j];
        }
        __syncthreads();
    }

    float bv[8];
    #pragma unroll
    for (int j = 0; j < 8; j++) bv[j] = bias[n0 + tn * 8 + j];

    #pragma unroll
    for (int i = 0; i < 8; i++) {
        float* crow = g_P + (size_t)(m0 + tm * 8 + i) * HID + n0 + tn * 8;
        float4 v0 = make_float4(acc[i][0] + bv[0], acc[i][1] + bv[1],
                                acc[i][2] + bv[2], acc[i][3] + bv[3]);
        float4 v1 = make_float4(acc[i][4] + bv[4], acc[i][5] + bv[5],
                                acc[i][6] + bv[6], acc[i][7] + bv[7]);
        *(float4*)(crow)     = v0;
        *(float4*)(crow + 4) = v1;
    }
}

// ==============================================================================
// Persistent recurrence kernel for one layer.
//   h_t = tanh( g_P[b][t][:] + W_hh @ h_{t-1} + b_hh )
// Grid: 128 CTAs = 16 batch-groups (2 batches) x 8 j-groups (64 columns).
// W_hh slice (64 x 512) lives in registers (128 regs/thread).
// Cross-CTA h exchange within a batch group via L2 + fence/flag release-acquire.
// ==============================================================================
__global__ __launch_bounds__(256, 1) void rec_kernel(
    const float* __restrict__ Whh,        // [512][512] for this layer
    const float* __restrict__ h0l,        // [32][512]  for this layer
    const float* __restrict__ bhh,        // [512]      for this layer
    float* __restrict__ out_ext, int useO,
    float* __restrict__ hidden_out)       // [32][512]  for this layer
{
    float* outbuf = useO ? g_O : out_ext;

    int bg = blockIdx.x & (GB - 1);       // 0..15
    int jg = blockIdx.x >> 4;             // 0..7
    int b0 = bg * 2;
    int jbase = jg * 64;

    int tid = threadIdx.x;
    int w = tid >> 5;                     // warp 0..7 -> k-chunk of 64
    int l = tid & 31;                     // lane -> j = jbase + l (+32)

    __shared__ float2 h_sh[HID];          // h interleaved by batch: (b0, b1)
    __shared__ float  red[8][2][64];      // [k-chunk][batch][jlocal]
    __shared__ float  bias_sh[64];

    if (tid < 64) bias_sh[tid] = bhh[jbase + tid];

    // Load W_hh slice into registers: Wr0 -> row jbase+l, Wr1 -> row jbase+l+32
    float Wr0[64], Wr1[64];
    {
        const float4* r0 = (const float4*)(Whh + (size_t)(jbase + l) * HID + w * 64);
        const float4* r1 = (const float4*)(Whh + (size_t)(jbase + l + 32) * HID + w * 64);
        #pragma unroll
        for (int i = 0; i < 16; i++) {
            float4 v0 = r0[i];
            Wr0[4*i+0] = v0.x; Wr0[4*i+1] = v0.y; Wr0[4*i+2] = v0.z; Wr0[4*i+3] = v0.w;
            float4 v1 = r1[i];
            Wr1[4*i+0] = v1.x; Wr1[4*i+1] = v1.y; Wr1[4*i+2] = v1.z; Wr1[4*i+3] = v1.w;
        }
    }

    int ob = tid >> 6;                    // output batch (0/1) for tid<128
    int jl = tid & 63;                    // output column for tid<128

    for (int t = 0; t < SEQ; t++) {
        // Prefetch pre-activation for this step (off the critical path:
        // issued before the spin, consumed after compute).
        float pre_v = 0.f;
        if (tid < 128)
            pre_v = __ldg(g_P + ((size_t)(b0 + ob) * SEQ + t) * HID + jbase + jl);

        // ---- acquire h_{t-1} ----
        if (t == 0) {
            #pragma unroll
            for (int i = 0; i < 4; i++) {
                int e = tid + 256 * i;
                int b = e >> 9, k = e & 511;
                ((float*)h_sh)[k * 2 + b] = h0l[(size_t)(b0 + b) * HID + k];
            }
        } else {
            if (tid < GJ) {
                while (ld_acquire_gpu(&g_flags[bg * GJ + tid]) < t) __nanosleep(32);
            }
            __syncthreads();
            const float* hb = g_hbuf[(t - 1) & 1];
            #pragma unroll
            for (int i = 0; i < 4; i++) {
                int e = tid + 256 * i;
                int b = e >> 9, k = e & 511;
                ((float*)h_sh)[k * 2 + b] = hb[(size_t)(b0 + b) * HID + k];
            }
        }
        __syncthreads();

        // ---- partial dot products: this warp's 64-wide k chunk ----
        float a00 = 0.f, a01 = 0.f, a10 = 0.f, a11 = 0.f;
        const float2* hp = h_sh + w * 64;
        #pragma unroll
        for (int kk = 0; kk < 64; kk++) {
            float2 hv = hp[kk];                 // LDS.64 broadcast
            a00 += Wr0[kk] * hv.x;
            a01 += Wr0[kk] * hv.y;
            a10 += Wr1[kk] * hv.x;
            a11 += Wr1[kk] * hv.y;
        }
        red[w][0][l]      = a00;
        red[w][1][l]      = a01;
        red[w][0][l + 32] = a10;
        red[w][1][l + 32] = a11;
        __syncthreads();

        // ---- reduce 8 k-chunks, tanh, store ----
        if (tid < 128) {
            float s = pre_v + bias_sh[jl];
            #pragma unroll
            for (int ww = 0; ww < 8; ww++) s += red[ww][ob][jl];
            float val = tanhf(s);

            int gb = b0 + ob;
            int gj = jbase + jl;
            g_hbuf[t & 1][(size_t)gb * HID + gj] = val;
            outbuf[((size_t)gb * SEQ + t) * HID + gj] = val;
            if (t == SEQ - 1)
                hidden_out[(size_t)gb * HID + gj] = val;
        }
        __syncthreads();

        // ---- release: publish h_t to peer CTAs of this batch group ----
        if (tid == 0) {
            __threadfence();                       // cumulative gpu-scope fence
            st_relaxed_gpu(&g_flags[bg * GJ + jg], t + 1);
        }
    }
}

// ==============================================================================
extern "C" void kernel_launch(void* const* d_in, const int* in_sizes, int n_in,
                              void* d_out, int out_size)
{
    const float* x     = (const float*)d_in[0];   // [32,1024,128]
    const float* h0    = (const float*)d_in[1];   // [3,32,512]
    const float* w_ih0 = (const float*)d_in[2];   // [512,128]
    const float* w_ihs = (const float*)d_in[3];   // [2,512,512]
    const float* w_hhs = (const float*)d_in[4];   // [3,512,512]
    const float* b_ihs = (const float*)d_in[5];   // [3,512]
    const float* b_hhs = (const float*)d_in[6];   // [3,512]

    float* out    = (float*)d_out;
    float* hidden = out;                                   // [3][32][512]
    float* outseq = out + (size_t)LAYERS * BATCH * HID;    // [32*1024][512]

    dim3 pg(HID / 128, (BATCH * SEQ) / 128);               // (4, 256)

    // ---- layer 0 ----
    proj_kernel<<<pg, 256>>>(x, /*useO=*/0, w_ih0, b_ihs + 0 * HID, INDIM);
    rec_kernel<<<GB * GJ, 256>>>(w_hhs + (size_t)0 * HID * HID,
                                 h0 + (size_t)0 * BATCH * HID,
                                 b_hhs + 0 * HID,
                                 nullptr, /*useO=*/1,
                                 hidden + (size_t)0 * BATCH * HID);
    // ---- layer 1 ----
    proj_kernel<<<pg, 256>>>(nullptr, /*useO=*/1, w_ihs + (size_t)0 * HID * HID,
                             b_ihs + 1 * HID, HID);
    rec_kernel<<<GB * GJ, 256>>>(w_hhs + (size_t)1 * HID * HID,
                                 h0 + (size_t)1 * BATCH * HID,
                                 b_hhs + 1 * HID,
                                 nullptr, /*useO=*/1,
                                 hidden + (size_t)1 * BATCH * HID);
    // ---- layer 2 (writes sequence directly into d_out) ----
    proj_kernel<<<pg, 256>>>(nullptr, /*useO=*/1, w_ihs + (size_t)1 * HID * HID,
                             b_ihs + 2 * HID, HID);
    rec_kernel<<<GB * GJ, 256>>>(w_hhs + (size_t)2 * HID * HID,
                                 h0 + (size_t)2 * BATCH * HID,
                                 b_hhs + 2 * HID,
                                 outseq, /*useO=*/0,
                                 hidden + (size_t)2 * BATCH * HID);
}